// round 8
// baseline (speedup 1.0000x reference)
#include <cuda_runtime.h>
#include <cuda_bf16.h>
#include <math.h>
#include <stdint.h>

#define BATCH 64
#define SEQ 256
#define EMB 256
#define NHEAD 8
#define HEADD 32
#define MROWS (BATCH*SEQ)   /* 16384 */
#define ADIM 32

// ---------------- scratch (device globals; no allocation allowed) ------------
__device__ float g_x[MROWS*EMB];
__device__ float g_q[MROWS*EMB];
__device__ float g_k[MROWS*EMB];
__device__ float g_v[MROWS*EMB];
__device__ float g_g[MROWS*EMB];
__device__ float g_z[MROWS*EMB];
__device__ float g_t[MROWS*EMB];

__device__ __forceinline__ float gelu_tanh(float x){
    float x3 = x*x*x;
    return 0.5f*x*(1.f + tanhf(0.7978845608028654f*(x + 0.044715f*x3)));
}
__device__ __forceinline__ float swish_f(float x){
    return x / (1.f + expf(-x));
}

__device__ __forceinline__ uint32_t smem_u32(const void* p){
    uint32_t a;
    asm("{ .reg .u64 t; cvta.to.shared.u64 t, %1; cvt.u32.u64 %0, t; }" : "=r"(a) : "l"(p));
    return a;
}

// bf16 hi/lo split of two floats, packed as bf16x2 words (memory order a,b)
__device__ __forceinline__ uint32_t pack2(float a, float b, uint32_t& lo){
    __nv_bfloat16 ha = __float2bfloat16(a), hb = __float2bfloat16(b);
    __nv_bfloat16 la = __float2bfloat16(a - __bfloat162float(ha));
    __nv_bfloat16 lb = __float2bfloat16(b - __bfloat162float(hb));
    lo = (uint32_t)__bfloat16_as_ushort(la) | ((uint32_t)__bfloat16_as_ushort(lb)<<16);
    return (uint32_t)__bfloat16_as_ushort(ha) | ((uint32_t)__bfloat16_as_ushort(hb)<<16);
}

#define LDSM4(r, addr) \
    asm volatile("ldmatrix.sync.aligned.m8n8.x4.shared.b16 {%0,%1,%2,%3}, [%4];" \
        : "=r"((r)[0]),"=r"((r)[1]),"=r"((r)[2]),"=r"((r)[3]) : "r"(addr))
#define LDSM2(r, addr) \
    asm volatile("ldmatrix.sync.aligned.m8n8.x2.shared.b16 {%0,%1}, [%2];" \
        : "=r"((r)[0]),"=r"((r)[1]) : "r"(addr))
#define LDSM2T(r, addr) \
    asm volatile("ldmatrix.sync.aligned.m8n8.x2.trans.shared.b16 {%0,%1}, [%2];" \
        : "=r"((r)[0]),"=r"((r)[1]) : "r"(addr))
#define MMA16816(c, a, b) \
    asm volatile("mma.sync.aligned.m16n8k16.row.col.f32.bf16.bf16.f32 " \
        "{%0,%1,%2,%3}, {%4,%5,%6,%7}, {%8,%9}, {%0,%1,%2,%3};" \
        : "+f"((c)[0]),"+f"((c)[1]),"+f"((c)[2]),"+f"((c)[3]) \
        : "r"((a)[0]),"r"((a)[1]),"r"((a)[2]),"r"((a)[3]), "r"((b)[0]),"r"((b)[1]))

// ---------------- bf16x3 HGEMM, 64x256 tile, fused epilogues -----------------
// CTA: 64(M) x 256(N), 8 warps (2 m x 4 n), warp 32x64. BK=32, double-buffered.
// EPI: 0 none
//      2 swish(acc)*aux
//      3 acc+bias
//      4 rmsnorm(aux_row + acc) * ln          (residual + rmsnorm fused)
//      5 rmsnorm(gelu(acc + bias)) * ln
struct GemmP {
    const float* A;
    const float* B0; const float* B1; const float* B2; const float* B3;
    float* C0; float* C1; float* C2; float* C3;
    const float* bias; const float* aux; const float* ln;
    int N; int K;
};

#define AH_SZ 5120                     /* 64 rows x 80B  */
#define BH_SZ 16896                    /* 32 rows x 528B */
#define BUF_SZ (2*AH_SZ + 2*BH_SZ)     /* 44032 */
#define SMEMSZ (2*BUF_SZ)              /* 88064 */

template<int EPI>
__global__ __launch_bounds__(256,2)
void hgemm(GemmP p)
{
    extern __shared__ char smem[];
    const uint32_t sb = smem_u32(smem);
    const int tid = threadIdx.x;
    const int lane = tid&31, warp = tid>>5;
    const int wm = warp&1, wn = warp>>1;
    const int bm0 = blockIdx.x*64;
    const int N = p.N, K = p.K;
    const int mi = blockIdx.y;
    const float* __restrict__ B = (mi==0)?p.B0 : (mi==1)?p.B1 : (mi==2)?p.B2 : p.B3;
    float* __restrict__ C       = (mi==0)?p.C0 : (mi==1)?p.C1 : (mi==2)?p.C2 : p.C3;
    const int nc = K>>5;

    float acc[2][8][4];
    #pragma unroll
    for (int mt=0;mt<2;mt++)
        #pragma unroll
        for (int j=0;j<8;j++)
            #pragma unroll
            for (int e=0;e<4;e++) acc[mt][j][e]=0.f;

    const int arow = tid>>2, akseg = (tid&3)*8;   // A: 64 rows x 32 k
    const int bk = tid>>3, bnn = (tid&7)*32;      // B: 32 k x 256 n

    uint32_t aH[4], aL[4], bH[8], bL[8];

    auto loadG = [&](int c){
        const float* Ap = p.A + (size_t)(bm0+arow)*K + c*32 + akseg;
        float4 x0 = *(const float4*)Ap;
        float4 x1 = *(const float4*)(Ap+4);
        aH[0] = pack2(x0.x,x0.y,aL[0]);
        aH[1] = pack2(x0.z,x0.w,aL[1]);
        aH[2] = pack2(x1.x,x1.y,aL[2]);
        aH[3] = pack2(x1.z,x1.w,aL[3]);
        if (bnn + 32 <= N){
            const float* Bp = B + (size_t)(c*32+bk)*N + bnn;
            #pragma unroll
            for (int i=0;i<4;i++){
                float4 y0 = *(const float4*)(Bp + 8*i);
                float4 y1 = *(const float4*)(Bp + 8*i + 4);
                bH[2*i+0] = pack2(y0.x,y0.y,bL[2*i+0]);
                bH[2*i+1] = pack2(y0.z,y0.w,bL[2*i+1]);
                // pack y1 into next pair below
                uint32_t lo2, lo3;
                uint32_t h2 = pack2(y1.x,y1.y,lo2);
                uint32_t h3 = pack2(y1.z,y1.w,lo3);
                // shift: we produce 4 words per 8 floats; lay out linearly
                // words for this i: [2i,2i+1] from y0 — wrong stride; fix below
                (void)h2; (void)h3; (void)lo2; (void)lo3;
            }
            // relinear: do it simply with a scalar loop over 16 pairs
            const float* Bf = Bp;
            #pragma unroll
            for (int w=0; w<8; w++){
                bH[w] = pack2(Bf[4*w+0], Bf[4*w+1], bL[w]);
                // NOTE: pairs (4w,4w+1) and (4w+2,4w+3) both needed; handled below
            }
            // Correct full packing: 32 floats -> 16 bf16x2 words; we only have 8
            // slots, so pack pairs (2w, 2w+1) of consecutive floats:
            #pragma unroll
            for (int w=0; w<8; w++){
                bH[w] = pack2(Bf[4*w+0], Bf[4*w+1], bL[w]);
            }
        } else {
            #pragma unroll
            for (int w=0;w<8;w++){ bH[w]=0u; bL[w]=0u; }
        }
    };
    // The above B packing covers only half the data (8 words = 16 floats of 32).
    // Use a second staging pair:
    uint32_t bH2[8], bL2[8];
    auto loadGB2 = [&](int c){
        if (bnn + 32 <= N){
            const float* Bp = B + (size_t)(c*32+bk)*N + bnn;
            #pragma unroll
            for (int w=0; w<8; w++)
                bH2[w] = pack2(Bp[4*w+2], Bp[4*w+3], bL2[w]);
        } else {
            #pragma unroll
            for (int w=0;w<8;w++){ bH2[w]=0u; bL2[w]=0u; }
        }
    };

    auto storeS = [&](int buf){
        char* ah = smem + buf*BUF_SZ + arow*80 + akseg*2;
        *(uint4*)ah            = make_uint4(aH[0],aH[1],aH[2],aH[3]);
        *(uint4*)(ah + AH_SZ)  = make_uint4(aL[0],aL[1],aL[2],aL[3]);
        char* bh = smem + buf*BUF_SZ + 2*AH_SZ + bk*528 + bnn*2;
        // interleave the two staging sets back into memory order:
        // floats [4w,4w+1] -> word bH[w] ; [4w+2,4w+3] -> bH2[w]
        #pragma unroll
        for (int w=0; w<4; w++){
            *(uint4*)(bh + 16*w) = make_uint4(bH[2*w], bH2[2*w], bH[2*w+1], bH2[2*w+1]);
            *(uint4*)(bh + BH_SZ + 16*w) = make_uint4(bL[2*w], bL2[2*w], bL[2*w+1], bL2[2*w+1]);
        }
    };

    loadG(0); loadGB2(0); storeS(0);
    __syncthreads();

    for (int c=0; c<nc; c++){
        const int buf = c&1;
        const bool more = (c+1 < nc);
        if (more){ loadG(c+1); loadGB2(c+1); }

        const uint32_t sA  = sb + buf*BUF_SZ;
        const uint32_t sAl = sA + AH_SZ;
        const uint32_t sB  = sA + 2*AH_SZ;
        const uint32_t sBl = sB + BH_SZ;
        const uint32_t aro = (uint32_t)(wm*32 + (lane&15));

        #pragma unroll
        for (int kt=0; kt<2; kt++){
            uint32_t ah2[2][4], al2[2][4];
            #pragma unroll
            for (int mt=0; mt<2; mt++){
                const uint32_t ao = (aro + mt*16)*80 + (uint32_t)(kt*16 + (lane>>4)*8)*2;
                LDSM4(ah2[mt], sA  + ao);
                LDSM4(al2[mt], sAl + ao);
            }
            const uint32_t brow = (uint32_t)(kt*16) + (uint32_t)(lane&15);
            #pragma unroll
            for (int jn=0; jn<8; jn++){
                const uint32_t bo = brow*528 + (uint32_t)(wn*64 + jn*8)*2;
                uint32_t bh2[2], bl2[2];
                LDSM2T(bh2, sB  + bo);
                LDSM2T(bl2, sBl + bo);
                #pragma unroll
                for (int mt=0; mt<2; mt++){
                    MMA16816(acc[mt][jn], ah2[mt], bh2);
                    MMA16816(acc[mt][jn], al2[mt], bh2);
                    MMA16816(acc[mt][jn], ah2[mt], bl2);
                }
            }
        }
        if (more) storeS(buf^1);
        __syncthreads();
    }

    const int g = lane>>2, tq = lane&3;

    if (EPI <= 3){
        #pragma unroll
        for (int mt=0; mt<2; mt++){
            #pragma unroll
            for (int jn=0; jn<8; jn++){
                const int col = wn*64 + jn*8 + tq*2;
                if (col < N){
                    #pragma unroll
                    for (int half=0; half<2; half++){
                        const int row = bm0 + wm*32 + mt*16 + g + half*8;
                        float v0 = acc[mt][jn][2*half+0];
                        float v1 = acc[mt][jn][2*half+1];
                        if (EPI==2){
                            const float2 xa = *(const float2*)(p.aux + (size_t)row*N + col);
                            v0 = swish_f(v0)*xa.x; v1 = swish_f(v1)*xa.y;
                        } else if (EPI==3){
                            v0 += p.bias[col]; v1 += p.bias[col+1];
                        }
                        *(float2*)(C + (size_t)row*N + col) = make_float2(v0,v1);
                    }
                }
            }
        }
    } else {
        // fused rmsnorm epilogues (N==256 guaranteed)
        float ss[2][2] = {{0.f,0.f},{0.f,0.f}};
        #pragma unroll
        for (int mt=0; mt<2; mt++){
            #pragma unroll
            for (int half=0; half<2; half++){
                const int row = bm0 + wm*32 + mt*16 + g + half*8;
                #pragma unroll
                for (int jn=0; jn<8; jn++){
                    const int col = wn*64 + jn*8 + tq*2;
                    float v0 = acc[mt][jn][2*half+0];
                    float v1 = acc[mt][jn][2*half+1];
                    if (EPI==4){
                        const float2 rr = *(const float2*)(p.aux + (size_t)row*EMB + col);
                        v0 += rr.x; v1 += rr.y;
                    } else { // EPI==5
                        if (p.bias){ v0 += p.bias[col]; v1 += p.bias[col+1]; }
                        v0 = gelu_tanh(v0); v1 = gelu_tanh(v1);
                    }
                    acc[mt][jn][2*half+0] = v0;
                    acc[mt][jn][2*half+1] = v1;
                    ss[mt][half] += v0*v0 + v1*v1;
                }
            }
        }
        #pragma unroll
        for (int mt=0; mt<2; mt++)
            #pragma unroll
            for (int half=0; half<2; half++){
                ss[mt][half] += __shfl_xor_sync(0xffffffffu, ss[mt][half], 1);
                ss[mt][half] += __shfl_xor_sync(0xffffffffu, ss[mt][half], 2);
            }
        float* rs = (float*)smem;
        if (tq == 0){
            #pragma unroll
            for (int mt=0; mt<2; mt++)
                #pragma unroll
                for (int half=0; half<2; half++){
                    const int rl = wm*32 + mt*16 + half*8 + g;
                    rs[rl*4 + wn] = ss[mt][half];
                }
        }
        __syncthreads();
        #pragma unroll
        for (int mt=0; mt<2; mt++){
            #pragma unroll
            for (int half=0; half<2; half++){
                const int rl = wm*32 + mt*16 + half*8 + g;
                const float tot = rs[rl*4+0]+rs[rl*4+1]+rs[rl*4+2]+rs[rl*4+3];
                const float rstd = rsqrtf(tot*(1.f/256.f) + 1e-6f);
                const int row = bm0 + rl;
                #pragma unroll
                for (int jn=0; jn<8; jn++){
                    const int col = wn*64 + jn*8 + tq*2;
                    const float2 lw = *(const float2*)(p.ln + col);
                    float v0 = acc[mt][jn][2*half+0]*rstd*lw.x;
                    float v1 = acc[mt][jn][2*half+1]*rstd*lw.y;
                    *(float2*)(C + (size_t)row*EMB + col) = make_float2(v0,v1);
                }
            }
        }
    }
}

// ---------------- tensor-core retention attention (unchanged, validated) -----
#define QROW 80
__global__ __launch_bounds__(256,2)
void attn_tc(const float* __restrict__ q, const float* __restrict__ k,
             const float* __restrict__ v, const float* __restrict__ g,
             const float* __restrict__ gns, const float* __restrict__ gnb,
             float* __restrict__ z)
{
    __shared__ __align__(16) char sQh[128*QROW];
    __shared__ __align__(16) char sQl[128*QROW];
    __shared__ __align__(16) char sKh[64*QROW];
    __shared__ __align__(16) char sKl[64*QROW];
    __shared__ __align__(16) char sVh[64*QROW];
    __shared__ __align__(16) char sVl[64*QROW];
    __shared__ float pg[32], pgi[32];

    const int b = blockIdx.z, h = blockIdx.y, rt = blockIdx.x;
    const int tid = threadIdx.x;
    const int lane = tid&31, wid = tid>>5;

    if (tid < 32){
        float lg = -3.4657359027997265f + (float)h * (-0.39608410032853687f);
        float gamma = 1.f - expf(lg);
        pg[tid]  = powf(gamma, (float)tid) * 0.17677669529663687f;
        pgi[tid] = powf(gamma, -(float)tid);
    }
    __syncthreads();

    {
        const int row = tid>>1, seg = (tid&1)*16;
        const int n = rt*128 + row;
        const float qs = pg[n>>3];
        const float* Qp = q + (size_t)(b*SEQ + n)*EMB + h*HEADD + seg;
        char* qh = sQh + row*QROW + seg*2;
        char* ql = sQl + row*QROW + seg*2;
        #pragma unroll
        for (int i=0;i<4;i++){
            float4 x4 = *(const float4*)(Qp + 4*i);
            uint2 hi, lo;
            hi.x = pack2(x4.x*qs, x4.y*qs, lo.x);
            hi.y = pack2(x4.z*qs, x4.w*qs, lo.y);
            *(uint2*)(qh + 8*i) = hi;
            *(uint2*)(ql + 8*i) = lo;
        }
    }
    __syncthreads();

    uint32_t qfh[2][4], qfl[2][4];
    {
        const uint32_t qb = smem_u32(sQh), qlb = smem_u32(sQl);
        const uint32_t aro = (uint32_t)(wid*16 + (lane&15));
        #pragma unroll
        for (int kt=0; kt<2; kt++){
            const uint32_t ao = aro*QROW + (uint32_t)(kt*16 + (lane>>4)*8)*2;
            LDSM4(qfh[kt], qb + ao);
            LDSM4(qfl[kt], qlb + ao);
        }
    }

    float oacc[4][4];
    #pragma unroll
    for (int jn=0;jn<4;jn++)
        #pragma unroll
        for (int e=0;e<4;e++) oacc[jn][e]=0.f;

    const int rowbase = rt*128 + wid*16;
    const int nchunks = 2*(rt+1);

    const uint32_t kb  = smem_u32(sKh), klb = smem_u32(sKl);
    const uint32_t vb  = smem_u32(sVh), vlb = smem_u32(sVl);

    for (int mc=0; mc<nchunks; mc++){
        __syncthreads();
        {
            const int row = tid>>2, seg = (tid&3)*8;
            const int m = mc*64 + row;
            const float ks = pgi[m>>3];
            const size_t base = (size_t)(b*SEQ + m)*EMB + h*HEADD + seg;
            float4 k0 = *(const float4*)(k + base);
            float4 k1 = *(const float4*)(k + base + 4);
            float4 v0 = *(const float4*)(v + base);
            float4 v1 = *(const float4*)(v + base + 4);
            char* kh = sKh + row*QROW + seg*2;
            char* kl = sKl + row*QROW + seg*2;
            char* vh = sVh + row*QROW + seg*2;
            char* vl = sVl + row*QROW + seg*2;
            uint2 hi, lo;
            hi.x = pack2(k0.x*ks, k0.y*ks, lo.x);
            hi.y = pack2(k0.z*ks, k0.w*ks, lo.y);
            *(uint2*)kh = hi; *(uint2*)kl = lo;
            hi.x = pack2(k1.x*ks, k1.y*ks, lo.x);
            hi.y = pack2(k1.z*ks, k1.w*ks, lo.y);
            *(uint2*)(kh+8) = hi; *(uint2*)(kl+8) = lo;
            hi.x = pack2(v0.x, v0.y, lo.x);
            hi.y = pack2(v0.z, v0.w, lo.y);
            *(uint2*)vh = hi; *(uint2*)vl = lo;
            hi.x = pack2(v1.x, v1.y, lo.x);
            hi.y = pack2(v1.z, v1.w, lo.y);
            *(uint2*)(vh+8) = hi; *(uint2*)(vl+8) = lo;
        }
        __syncthreads();

        const int mbase = mc*64;
        if (mbase > rowbase + 15) continue;

        float sacc[8][4];
        #pragma unroll
        for (int j=0;j<8;j++)
            #pragma unroll
            for (int e=0;e<4;e++) sacc[j][e]=0.f;

        #pragma unroll
        for (int kt=0; kt<2; kt++){
            #pragma unroll
            for (int j=0; j<8; j++){
                const uint32_t addr = (uint32_t)(j*8 + (lane&7))*QROW
                                    + (uint32_t)((lane>>3)&1)*16 + (uint32_t)kt*32;
                uint32_t kfh[2], kfl[2];
                LDSM2(kfh, kb  + addr);
                LDSM2(kfl, klb + addr);
                MMA16816(sacc[j], qfh[kt], kfh);
                MMA16816(sacc[j], qfl[kt], kfh);
                MMA16816(sacc[j], qfh[kt], kfl);
            }
        }

        if (mbase + 63 > rowbase){
            const int nr = rowbase + (lane>>2);
            const int mcb = mbase + (lane&3)*2;
            #pragma unroll
            for (int j=0;j<8;j++){
                const int m0 = mcb + j*8;
                if (m0   > nr)   sacc[j][0]=0.f;
                if (m0+1 > nr)   sacc[j][1]=0.f;
                if (m0   > nr+8) sacc[j][2]=0.f;
                if (m0+1 > nr+8) sacc[j][3]=0.f;
            }
        }

        #pragma unroll
        for (int kt2=0; kt2<4; kt2++){
            uint32_t ah[4], al[4];
            ah[0] = pack2(sacc[2*kt2][0],   sacc[2*kt2][1],   al[0]);
            ah[1] = pack2(sacc[2*kt2][2],   sacc[2*kt2][3],   al[1]);
            ah[2] = pack2(sacc[2*kt2+1][0], sacc[2*kt2+1][1], al[2]);
            ah[3] = pack2(sacc[2*kt2+1][2], sacc[2*kt2+1][3], al[3]);
            #pragma unroll
            for (int jn=0; jn<4; jn++){
                const uint32_t addr = (uint32_t)(kt2*16 + (lane&15))*QROW
                                    + (uint32_t)(jn*8)*2;
                uint32_t vfh[2], vfl[2];
                LDSM2T(vfh, vb  + addr);
                LDSM2T(vfl, vlb + addr);
                MMA16816(oacc[jn], ah, vfh);
                MMA16816(oacc[jn], al, vfh);
                MMA16816(oacc[jn], ah, vfl);
            }
        }
    }

    const int gl = lane>>2, tq = lane&3;
    float sum0=0.f, sum1=0.f;
    #pragma unroll
    for (int jn=0;jn<4;jn++){
        sum0 += oacc[jn][0] + oacc[jn][1];
        sum1 += oacc[jn][2] + oacc[jn][3];
    }
    sum0 += __shfl_xor_sync(0xffffffffu, sum0, 1);
    sum0 += __shfl_xor_sync(0xffffffffu, sum0, 2);
    sum1 += __shfl_xor_sync(0xffffffffu, sum1, 1);
    sum1 += __shfl_xor_sync(0xffffffffu, sum1, 2);
    const float mu0 = sum0*(1.f/32.f), mu1 = sum1*(1.f/32.f);
    float v0=0.f, v1=0.f;
    #pragma unroll
    for (int jn=0;jn<4;jn++){
        float d0 = oacc[jn][0]-mu0, d1 = oacc[jn][1]-mu0;
        float d2 = oacc[jn][2]-mu1, d3 = oacc[jn][3]-mu1;
        v0 += d0*d0 + d1*d1;
        v1 += d2*d2 + d3*d3;
    }
    v0 += __shfl_xor_sync(0xffffffffu, v0, 1);
    v0 += __shfl_xor_sync(0xffffffffu, v0, 2);
    v1 += __shfl_xor_sync(0xffffffffu, v1, 1);
    v1 += __shfl_xor_sync(0xffffffffu, v1, 2);
    const float inv0 = rsqrtf(v0*(1.f/32.f) + 1e-5f);
    const float inv1 = rsqrtf(v1*(1.f/32.f) + 1e-5f);

    const int n0 = rowbase + gl;
    const size_t base0 = (size_t)(b*SEQ + n0)*EMB + h*HEADD;
    const size_t base1 = base0 + 8*EMB;
    #pragma unroll
    for (int jn=0;jn<4;jn++){
        const int c = jn*8 + tq*2;
        const float2 gs = *(const float2*)(gns + h*HEADD + c);
        const float2 gb2 = *(const float2*)(gnb + h*HEADD + c);
        float2 gg0 = *(const float2*)(g + base0 + c);
        float2 gg1 = *(const float2*)(g + base1 + c);
        float y0 = (oacc[jn][0]-mu0)*inv0*gs.x + gb2.x;
        float y1 = (oacc[jn][1]-mu0)*inv0*gs.y + gb2.y;
        float y2 = (oacc[jn][2]-mu1)*inv1*gs.x + gb2.x;
        float y3 = (oacc[jn][3]-mu1)*inv1*gs.y + gb2.y;
        *(float2*)(z + base0 + c) = make_float2(swish_f(gg0.x)*y0, swish_f(gg0.y)*y1);
        *(float2*)(z + base1 + c) = make_float2(swish_f(gg1.x)*y2, swish_f(gg1.y)*y3);
    }
}

// ---------------- launcher ---------------------------------------------------
static inline GemmP mkp(const float* A, const float* B0, float* C0,
                        const float* bias, const float* aux, const float* ln,
                        int N, int K){
    GemmP p{}; p.A=A; p.B0=B0; p.C0=C0; p.bias=bias; p.aux=aux; p.ln=ln;
    p.N=N; p.K=K;
    return p;
}

extern "C" void kernel_launch(void* const* d_in, const int* in_sizes, int n_in,
                              void* d_out, int out_size)
{
    (void)in_sizes; (void)n_in; (void)out_size;
    const float* action = (const float*)d_in[0];
    const float* obs    = (const float*)d_in[1];
    const float* w_enc  = (const float*)d_in[2];
    const float* ln0    = (const float*)d_in[3];
    const float* wq1    = (const float*)d_in[4];
    const float* wk1    = (const float*)d_in[5];
    const float* wv1    = (const float*)d_in[6];
    const float* wg1    = (const float*)d_in[7];
    const float* wo1    = (const float*)d_in[8];
    const float* gns1   = (const float*)d_in[9];
    const float* gnb1   = (const float*)d_in[10];
    const float* ln1    = (const float*)d_in[11];
    const float* wq2    = (const float*)d_in[12];
    const float* wk2    = (const float*)d_in[13];
    const float* wv2    = (const float*)d_in[14];
    const float* wg2    = (const float*)d_in[15];
    const float* wo2    = (const float*)d_in[16];
    const float* gns2   = (const float*)d_in[17];
    const float* gnb2   = (const float*)d_in[18];
    const float* ln2    = (const float*)d_in[19];
    const float* swg    = (const float*)d_in[20];
    const float* sw1    = (const float*)d_in[21];
    const float* sw2    = (const float*)d_in[22];
    const float* ln3    = (const float*)d_in[23];
    const float* hw1    = (const float*)d_in[24];
    const float* hb1    = (const float*)d_in[25];
    const float* hln    = (const float*)d_in[26];
    const float* hw2    = (const float*)d_in[27];
    const float* hb2    = (const float*)d_in[28];
    float* out = (float*)d_out;

    float *x,*qb,*kb,*vb,*gb,*zb,*tb;
    cudaGetSymbolAddress((void**)&x,  g_x);
    cudaGetSymbolAddress((void**)&qb, g_q);
    cudaGetSymbolAddress((void**)&kb, g_k);
    cudaGetSymbolAddress((void**)&vb, g_v);
    cudaGetSymbolAddress((void**)&gb, g_g);
    cudaGetSymbolAddress((void**)&zb, g_z);
    cudaGetSymbolAddress((void**)&tb, g_t);

    cudaFuncSetAttribute(hgemm<0>, cudaFuncAttributeMaxDynamicSharedMemorySize, SMEMSZ);
    cudaFuncSetAttribute(hgemm<2>, cudaFuncAttributeMaxDynamicSharedMemorySize, SMEMSZ);
    cudaFuncSetAttribute(hgemm<3>, cudaFuncAttributeMaxDynamicSharedMemorySize, SMEMSZ);
    cudaFuncSetAttribute(hgemm<4>, cudaFuncAttributeMaxDynamicSharedMemorySize, SMEMSZ);
    cudaFuncSetAttribute(hgemm<5>, cudaFuncAttributeMaxDynamicSharedMemorySize, SMEMSZ);

    const dim3 g1(MROWS/64, 1);
    const dim3 g2(MROWS/64, 2);
    const dim3 g4(MROWS/64, 4);
    const dim3 gAttn(SEQ/128, NHEAD, BATCH);

    // encoder: x = rmsnorm(gelu(action @ w_enc)) * ln0   (fused)
    hgemm<5><<<g1,256,SMEMSZ>>>(mkp(action, w_enc, x, nullptr, nullptr, ln0, EMB, ADIM));

    for (int blk=0; blk<3; blk++){
        const size_t wOff = (size_t)blk*EMB*EMB;
        const size_t vOff = (size_t)blk*EMB;

        // retention 1 (self): batched q/k/v/g projections
        {
            GemmP p{};
            p.A = x;
            p.B0 = wq1+wOff; p.B1 = wk1+wOff; p.B2 = wv1+wOff; p.B3 = wg1+wOff;
            p.C0 = qb; p.C1 = kb; p.C2 = vb; p.C3 = gb;
            p.N = EMB; p.K = EMB;
            hgemm<0><<<g4,256,SMEMSZ>>>(p);
        }
        attn_tc<<<gAttn,256>>>(qb, kb, vb, gb, gns1+vOff, gnb1+vOff, zb);
        // x = rmsnorm(x + zb@wo1) * ln1   (fused)
        hgemm<4><<<g1,256,SMEMSZ>>>(mkp(zb, wo1+wOff, x, nullptr, x, ln1+vOff, EMB, EMB));

        // retention 2 (cross): k/v from x, q/g from obs_rep
        {
            GemmP p{};
            p.A = x;
            p.B0 = wk2+wOff; p.B1 = wv2+wOff;
            p.C0 = kb; p.C1 = vb;
            p.N = EMB; p.K = EMB;
            hgemm<0><<<g2,256,SMEMSZ>>>(p);
        }
        {
            GemmP p{};
            p.A = obs;
            p.B0 = wq2+wOff; p.B1 = wg2+wOff;
            p.C0 = qb; p.C1 = gb;
            p.N = EMB; p.K = EMB;
            hgemm<0><<<g2,256,SMEMSZ>>>(p);
        }
        attn_tc<<<gAttn,256>>>(qb, kb, vb, gb, gns2+vOff, gnb2+vOff, zb);
        // x = rmsnorm(obs + zb@wo2) * ln2   (fused)
        hgemm<4><<<g1,256,SMEMSZ>>>(mkp(zb, wo2+wOff, x, nullptr, obs, ln2+vOff, EMB, EMB));

        // swiglu
        hgemm<0><<<g1,256,SMEMSZ>>>(mkp(x, sw1+wOff, tb, nullptr, nullptr, nullptr, EMB, EMB));
        hgemm<2><<<g1,256,SMEMSZ>>>(mkp(x, swg+wOff, zb, nullptr, tb, nullptr, EMB, EMB));
        // x = rmsnorm(x + zb@sw2) * ln3   (fused)
        hgemm<4><<<g1,256,SMEMSZ>>>(mkp(zb, sw2+wOff, x, nullptr, x, ln3+vOff, EMB, EMB));
    }

    // head: zb = rmsnorm(gelu(x@hw1 + hb1)) * hln  (fused), then out = zb@hw2 + hb2
    hgemm<5><<<g1,256,SMEMSZ>>>(mkp(x, hw1, zb, hb1, nullptr, hln, EMB, EMB));
    hgemm<3><<<g1,256,SMEMSZ>>>(mkp(zb, hw2, out, hb2, nullptr, nullptr, ADIM, EMB));
}

// round 9
// speedup vs baseline: 2.1625x; 2.1625x over previous
#include <cuda_runtime.h>
#include <cuda_bf16.h>
#include <math.h>
#include <stdint.h>

#define BATCH 64
#define SEQ 256
#define EMB 256
#define NHEAD 8
#define HEADD 32
#define MROWS (BATCH*SEQ)   /* 16384 */
#define ADIM 32
#define NSLOT 42
#define SLOT_SZ 65536

// ---------------- scratch (device globals; no allocation allowed) ------------
__device__ float g_x[MROWS*EMB];
__device__ float g_q[MROWS*EMB];
__device__ float g_k[MROWS*EMB];
__device__ float g_v[MROWS*EMB];
__device__ float g_g[MROWS*EMB];
__device__ float g_z[MROWS*EMB];
__device__ float g_t[MROWS*EMB];
__device__ __nv_bfloat16 g_xH[MROWS*EMB], g_xL[MROWS*EMB];
__device__ __nv_bfloat16 g_oH[MROWS*EMB], g_oL[MROWS*EMB];
__device__ __nv_bfloat16 g_zH[MROWS*EMB], g_zL[MROWS*EMB];
__device__ __nv_bfloat16 g_aH[MROWS*ADIM], g_aL[MROWS*ADIM];
__device__ __nv_bfloat16 g_wH[NSLOT*SLOT_SZ], g_wL[NSLOT*SLOT_SZ];

__device__ __forceinline__ float gelu_tanh(float x){
    float x3 = x*x*x;
    return 0.5f*x*(1.f + tanhf(0.7978845608028654f*(x + 0.044715f*x3)));
}
__device__ __forceinline__ float swish_f(float x){
    return x / (1.f + expf(-x));
}
__device__ __forceinline__ uint32_t smem_u32(const void* p){
    uint32_t a;
    asm("{ .reg .u64 t; cvta.to.shared.u64 t, %1; cvt.u32.u64 %0, t; }" : "=r"(a) : "l"(p));
    return a;
}
// bf16 hi/lo split of two floats, packed as bf16x2 words (memory order a,b)
__device__ __forceinline__ uint32_t pack2(float a, float b, uint32_t& lo){
    __nv_bfloat16 ha = __float2bfloat16(a), hb = __float2bfloat16(b);
    __nv_bfloat16 la = __float2bfloat16(a - __bfloat162float(ha));
    __nv_bfloat16 lb = __float2bfloat16(b - __bfloat162float(hb));
    lo = (uint32_t)__bfloat16_as_ushort(la) | ((uint32_t)__bfloat16_as_ushort(lb)<<16);
    return (uint32_t)__bfloat16_as_ushort(ha) | ((uint32_t)__bfloat16_as_ushort(hb)<<16);
}

#define LDSM4(r, addr) \
    asm volatile("ldmatrix.sync.aligned.m8n8.x4.shared.b16 {%0,%1,%2,%3}, [%4];" \
        : "=r"((r)[0]),"=r"((r)[1]),"=r"((r)[2]),"=r"((r)[3]) : "r"(addr))
#define LDSM2(r, addr) \
    asm volatile("ldmatrix.sync.aligned.m8n8.x2.shared.b16 {%0,%1}, [%2];" \
        : "=r"((r)[0]),"=r"((r)[1]) : "r"(addr))
#define LDSM2T(r, addr) \
    asm volatile("ldmatrix.sync.aligned.m8n8.x2.trans.shared.b16 {%0,%1}, [%2];" \
        : "=r"((r)[0]),"=r"((r)[1]) : "r"(addr))
#define MMA16816(c, a, b) \
    asm volatile("mma.sync.aligned.m16n8k16.row.col.f32.bf16.bf16.f32 " \
        "{%0,%1,%2,%3}, {%4,%5,%6,%7}, {%8,%9}, {%0,%1,%2,%3};" \
        : "+f"((c)[0]),"+f"((c)[1]),"+f"((c)[2]),"+f"((c)[3]) \
        : "r"((a)[0]),"r"((a)[1]),"r"((a)[2]),"r"((a)[3]), "r"((b)[0]),"r"((b)[1]))
#define CPA16(dst, src) \
    asm volatile("cp.async.cg.shared.global [%0],[%1],16;" :: "r"(dst),"l"(src))
#define CPA16Z(dst, src, sz) \
    asm volatile("cp.async.cg.shared.global [%0],[%1],16,%2;" :: "r"(dst),"l"(src),"r"(sz))

// ---------------- conversion kernels -----------------------------------------
struct ConvW { const float* src[NSLOT]; int sz[NSLOT]; };
__global__ void conv_w(ConvW cw, __nv_bfloat16* wh, __nv_bfloat16* wl){
    const int slot = blockIdx.x;
    const int n = cw.sz[slot];
    const float* s = cw.src[slot];
    for (int i = blockIdx.y*blockDim.x + threadIdx.x; i < n; i += gridDim.y*blockDim.x){
        float v = s[i];
        __nv_bfloat16 h = __float2bfloat16(v);
        wh[slot*SLOT_SZ + i] = h;
        wl[slot*SLOT_SZ + i] = __float2bfloat16(v - __bfloat162float(h));
    }
}
__global__ void conv_a(const float* __restrict__ s, __nv_bfloat16* __restrict__ h,
                       __nv_bfloat16* __restrict__ l, int n){
    for (int i = blockIdx.x*blockDim.x + threadIdx.x; i < n; i += gridDim.x*blockDim.x){
        float v = s[i];
        __nv_bfloat16 hh = __float2bfloat16(v);
        h[i] = hh;
        l[i] = __float2bfloat16(v - __bfloat162float(hh));
    }
}

// ---------------- bf16x3 HGEMM, cp.async pipelined ---------------------------
// CTA: 128(M) x 64(N), 8 warps (4x2), warp 32x32. BK=32, 3-stage cp.async.
// A/B pre-split bf16 hi/lo in global. EPI: 0 none, 1 gelu(acc+bias?),
// 2 swish(acc)*aux -> bf16 hi/lo out, 3 acc+bias.
struct GemmP {
    const __nv_bfloat16 *AH[4], *AL[4];
    const __nv_bfloat16 *WH[4], *WL[4];
    float* C[4];
    __nv_bfloat16 *CH, *CL;
    const float* bias; const float* aux;
    int N; int K;
};

#define STG 29696      /* A_h 128*80 + A_l + B_h 32*144 + B_l */
#define OFF_AL 10240
#define OFF_BH 20480
#define OFF_BL 25088
#define SMEM_TOT (3*STG)   /* 89088 */

template<int EPI>
__global__ __launch_bounds__(256,2)
void hgemm(GemmP p)
{
    extern __shared__ char smem[];
    const uint32_t sb = smem_u32(smem);
    const int tid = threadIdx.x;
    const int lane = tid&31, warp = tid>>5;
    const int wm = warp&3, wn = warp>>2;
    const int bm0 = blockIdx.x*128;
    const int N = p.N, K = p.K;
    const int NT = (N>=64) ? (N>>6) : 1;
    const int mi = blockIdx.y / NT;
    const int bn0 = (blockIdx.y % NT)*64;
    const __nv_bfloat16* __restrict__ AH = p.AH[mi];
    const __nv_bfloat16* __restrict__ AL = p.AL[mi];
    const __nv_bfloat16* __restrict__ WH = p.WH[mi];
    const __nv_bfloat16* __restrict__ WL = p.WL[mi];
    float* __restrict__ C = p.C[mi];
    const int nc = K>>5;

    float acc[2][4][4];
    #pragma unroll
    for (int mt=0;mt<2;mt++)
        #pragma unroll
        for (int j=0;j<4;j++)
            #pragma unroll
            for (int e=0;e<4;e++) acc[mt][j][e]=0.f;

    // cp.async task mapping
    const int ar0 = tid>>1, aq0 = (tid&1)*2;     // thread covers A rows ar0, chunks aq0,aq0+1
    const int br = tid>>3, bq = tid&7;
    const int bcol = bn0 + bq*8;
    const int bvalid = (bcol < N) ? 16 : 0;
    const int bcolc = (bcol < N) ? bcol : 0;

    auto issue = [&](int st){
        const uint32_t bs = sb + (uint32_t)((st%3)*STG);
        const size_t abase = (size_t)(bm0+ar0)*K + st*32;
        #pragma unroll
        for (int i=0;i<2;i++){
            const int qk = aq0 + i;
            const uint32_t dh = bs + ar0*80 + qk*16;
            CPA16(dh,          AH + abase + qk*8);
            CPA16(dh + OFF_AL, AL + abase + qk*8);
        }
        {
            const size_t wbase = (size_t)(st*32+br)*N + bcolc;
            const uint32_t dh = bs + OFF_BH + br*144 + bq*16;
            CPA16Z(dh,                     WH + wbase, bvalid);
            CPA16Z(dh + (OFF_BL-OFF_BH),   WL + wbase, bvalid);
        }
        asm volatile("cp.async.commit_group;" ::: "memory");
    };

    {
        const int npro = (nc < 2) ? nc : 2;
        for (int s=0; s<npro; s++) issue(s);
    }

    for (int c=0; c<nc; c++){
        if (c == nc-1) asm volatile("cp.async.wait_group 0;" ::: "memory");
        else           asm volatile("cp.async.wait_group 1;" ::: "memory");
        __syncthreads();

        const uint32_t sA  = sb + (uint32_t)((c%3)*STG);
        const uint32_t sAl = sA + OFF_AL;
        const uint32_t sB  = sA + OFF_BH;
        const uint32_t sBl = sA + OFF_BL;
        const uint32_t aro = (uint32_t)(wm*32 + (lane&15));
        const uint32_t bro = (uint32_t)(lane&15);

        #pragma unroll
        for (int s=0; s<2; s++){
            const uint32_t acol = (uint32_t)(s*16 + (lane>>4)*8)*2;
            uint32_t ah[2][4], al[2][4], bh[4][2], bl[4][2];
            #pragma unroll
            for (int mt=0; mt<2; mt++){
                const uint32_t ao = (aro + mt*16)*80 + acol;
                LDSM4(ah[mt], sA  + ao);
                LDSM4(al[mt], sAl + ao);
            }
            const uint32_t brow = (uint32_t)(s*16) + bro;
            #pragma unroll
            for (int j=0; j<4; j++){
                const uint32_t bo = brow*144 + (uint32_t)(wn*32 + j*8)*2;
                LDSM2T(bh[j], sB  + bo);
                LDSM2T(bl[j], sBl + bo);
            }
            #pragma unroll
            for (int mt=0; mt<2; mt++)
                #pragma unroll
                for (int j=0; j<4; j++)
                    MMA16816(acc[mt][j], ah[mt], bh[j]);
            #pragma unroll
            for (int mt=0; mt<2; mt++)
                #pragma unroll
                for (int j=0; j<4; j++)
                    MMA16816(acc[mt][j], ah[mt], bl[j]);
            #pragma unroll
            for (int mt=0; mt<2; mt++)
                #pragma unroll
                for (int j=0; j<4; j++)
                    MMA16816(acc[mt][j], al[mt], bh[j]);
        }
        __syncthreads();
        if (c+2 < nc) issue(c+2);
    }

    const int g = lane>>2, tq = lane&3;
    #pragma unroll
    for (int mt=0; mt<2; mt++){
        const int r0 = bm0 + wm*32 + mt*16 + g;
        #pragma unroll
        for (int j=0; j<4; j++){
            const int col = bn0 + wn*32 + j*8 + tq*2;
            if (col < N){
                #pragma unroll
                for (int half=0; half<2; half++){
                    const int row = r0 + half*8;
                    float v0 = acc[mt][j][2*half+0];
                    float v1 = acc[mt][j][2*half+1];
                    if (EPI==1){
                        if (p.bias){ v0 += p.bias[col]; v1 += p.bias[col+1]; }
                        v0 = gelu_tanh(v0); v1 = gelu_tanh(v1);
                        *(float2*)(C + (size_t)row*N + col) = make_float2(v0,v1);
                    } else if (EPI==2){
                        const float2 xa = *(const float2*)(p.aux + (size_t)row*N + col);
                        v0 = swish_f(v0)*xa.x; v1 = swish_f(v1)*xa.y;
                        uint32_t lo, hi = pack2(v0, v1, lo);
                        *(uint32_t*)(p.CH + (size_t)row*N + col) = hi;
                        *(uint32_t*)(p.CL + (size_t)row*N + col) = lo;
                    } else if (EPI==3){
                        v0 += p.bias[col]; v1 += p.bias[col+1];
                        *(float2*)(C + (size_t)row*N + col) = make_float2(v0,v1);
                    } else {
                        *(float2*)(C + (size_t)row*N + col) = make_float2(v0,v1);
                    }
                }
            }
        }
    }
}

// ---------------- tensor-core retention attention ----------------------------
#define QROW 80
__global__ __launch_bounds__(256,2)
void attn_tc(const float* __restrict__ q, const float* __restrict__ k,
             const float* __restrict__ v, const float* __restrict__ g,
             const float* __restrict__ gns, const float* __restrict__ gnb,
             __nv_bfloat16* __restrict__ zh, __nv_bfloat16* __restrict__ zl)
{
    __shared__ __align__(16) char sQh[128*QROW];
    __shared__ __align__(16) char sQl[128*QROW];
    __shared__ __align__(16) char sKh[64*QROW];
    __shared__ __align__(16) char sKl[64*QROW];
    __shared__ __align__(16) char sVh[64*QROW];
    __shared__ __align__(16) char sVl[64*QROW];
    __shared__ float pg[32], pgi[32];

    const int b = blockIdx.z, h = blockIdx.y, rt = blockIdx.x;
    const int tid = threadIdx.x;
    const int lane = tid&31, wid = tid>>5;

    if (tid < 32){
        float lg = -3.4657359027997265f + (float)h * (-0.39608410032853687f);
        float gamma = 1.f - expf(lg);
        pg[tid]  = powf(gamma, (float)tid) * 0.17677669529663687f;
        pgi[tid] = powf(gamma, -(float)tid);
    }
    __syncthreads();

    {
        const int row = tid>>1, seg = (tid&1)*16;
        const int n = rt*128 + row;
        const float qs = pg[n>>3];
        const float* Qp = q + (size_t)(b*SEQ + n)*EMB + h*HEADD + seg;
        char* qh = sQh + row*QROW + seg*2;
        char* ql = sQl + row*QROW + seg*2;
        #pragma unroll
        for (int i=0;i<4;i++){
            float4 x4 = *(const float4*)(Qp + 4*i);
            uint2 hi, lo;
            hi.x = pack2(x4.x*qs, x4.y*qs, lo.x);
            hi.y = pack2(x4.z*qs, x4.w*qs, lo.y);
            *(uint2*)(qh + 8*i) = hi;
            *(uint2*)(ql + 8*i) = lo;
        }
    }
    __syncthreads();

    uint32_t qfh[2][4], qfl[2][4];
    {
        const uint32_t qb = smem_u32(sQh), qlb = smem_u32(sQl);
        const uint32_t aro = (uint32_t)(wid*16 + (lane&15));
        #pragma unroll
        for (int kt=0; kt<2; kt++){
            const uint32_t ao = aro*QROW + (uint32_t)(kt*16 + (lane>>4)*8)*2;
            LDSM4(qfh[kt], qb + ao);
            LDSM4(qfl[kt], qlb + ao);
        }
    }

    float oacc[4][4];
    #pragma unroll
    for (int jn=0;jn<4;jn++)
        #pragma unroll
        for (int e=0;e<4;e++) oacc[jn][e]=0.f;

    const int rowbase = rt*128 + wid*16;
    const int nchunks = 2*(rt+1);

    const uint32_t kb  = smem_u32(sKh), klb = smem_u32(sKl);
    const uint32_t vb  = smem_u32(sVh), vlb = smem_u32(sVl);

    for (int mc=0; mc<nchunks; mc++){
        __syncthreads();
        {
            const int row = tid>>2, seg = (tid&3)*8;
            const int m = mc*64 + row;
            const float ks = pgi[m>>3];
            const size_t base = (size_t)(b*SEQ + m)*EMB + h*HEADD + seg;
            float4 k0 = *(const float4*)(k + base);
            float4 k1 = *(const float4*)(k + base + 4);
            float4 v0 = *(const float4*)(v + base);
            float4 v1 = *(const float4*)(v + base + 4);
            char* kh = sKh + row*QROW + seg*2;
            char* kl = sKl + row*QROW + seg*2;
            char* vh = sVh + row*QROW + seg*2;
            char* vl = sVl + row*QROW + seg*2;
            uint2 hi, lo;
            hi.x = pack2(k0.x*ks, k0.y*ks, lo.x);
            hi.y = pack2(k0.z*ks, k0.w*ks, lo.y);
            *(uint2*)kh = hi; *(uint2*)kl = lo;
            hi.x = pack2(k1.x*ks, k1.y*ks, lo.x);
            hi.y = pack2(k1.z*ks, k1.w*ks, lo.y);
            *(uint2*)(kh+8) = hi; *(uint2*)(kl+8) = lo;
            hi.x = pack2(v0.x, v0.y, lo.x);
            hi.y = pack2(v0.z, v0.w, lo.y);
            *(uint2*)vh = hi; *(uint2*)vl = lo;
            hi.x = pack2(v1.x, v1.y, lo.x);
            hi.y = pack2(v1.z, v1.w, lo.y);
            *(uint2*)(vh+8) = hi; *(uint2*)(vl+8) = lo;
        }
        __syncthreads();

        const int mbase = mc*64;
        if (mbase > rowbase + 15) continue;

        float sacc[8][4];
        #pragma unroll
        for (int j=0;j<8;j++)
            #pragma unroll
            for (int e=0;e<4;e++) sacc[j][e]=0.f;

        #pragma unroll
        for (int kt=0; kt<2; kt++){
            #pragma unroll
            for (int j=0; j<8; j++){
                const uint32_t addr = (uint32_t)(j*8 + (lane&7))*QROW
                                    + (uint32_t)((lane>>3)&1)*16 + (uint32_t)kt*32;
                uint32_t kfh[2], kfl[2];
                LDSM2(kfh, kb  + addr);
                LDSM2(kfl, klb + addr);
                MMA16816(sacc[j], qfh[kt], kfh);
                MMA16816(sacc[j], qfl[kt], kfh);
                MMA16816(sacc[j], qfh[kt], kfl);
            }
        }

        if (mbase + 63 > rowbase){
            const int nr = rowbase + (lane>>2);
            const int mcb = mbase + (lane&3)*2;
            #pragma unroll
            for (int j=0;j<8;j++){
                const int m0 = mcb + j*8;
                if (m0   > nr)   sacc[j][0]=0.f;
                if (m0+1 > nr)   sacc[j][1]=0.f;
                if (m0   > nr+8) sacc[j][2]=0.f;
                if (m0+1 > nr+8) sacc[j][3]=0.f;
            }
        }

        #pragma unroll
        for (int kt2=0; kt2<4; kt2++){
            uint32_t ah[4], al[4];
            ah[0] = pack2(sacc[2*kt2][0],   sacc[2*kt2][1],   al[0]);
            ah[1] = pack2(sacc[2*kt2][2],   sacc[2*kt2][3],   al[1]);
            ah[2] = pack2(sacc[2*kt2+1][0], sacc[2*kt2+1][1], al[2]);
            ah[3] = pack2(sacc[2*kt2+1][2], sacc[2*kt2+1][3], al[3]);
            #pragma unroll
            for (int jn=0; jn<4; jn++){
                const uint32_t addr = (uint32_t)(kt2*16 + (lane&15))*QROW
                                    + (uint32_t)(jn*8)*2;
                uint32_t vfh[2], vfl[2];
                LDSM2T(vfh, vb  + addr);
                LDSM2T(vfl, vlb + addr);
                MMA16816(oacc[jn], ah, vfh);
                MMA16816(oacc[jn], al, vfh);
                MMA16816(oacc[jn], ah, vfl);
            }
        }
    }

    const int gl = lane>>2, tq = lane&3;
    float sum0=0.f, sum1=0.f;
    #pragma unroll
    for (int jn=0;jn<4;jn++){
        sum0 += oacc[jn][0] + oacc[jn][1];
        sum1 += oacc[jn][2] + oacc[jn][3];
    }
    sum0 += __shfl_xor_sync(0xffffffffu, sum0, 1);
    sum0 += __shfl_xor_sync(0xffffffffu, sum0, 2);
    sum1 += __shfl_xor_sync(0xffffffffu, sum1, 1);
    sum1 += __shfl_xor_sync(0xffffffffu, sum1, 2);
    const float mu0 = sum0*(1.f/32.f), mu1 = sum1*(1.f/32.f);
    float v0=0.f, v1=0.f;
    #pragma unroll
    for (int jn=0;jn<4;jn++){
        float d0 = oacc[jn][0]-mu0, d1 = oacc[jn][1]-mu0;
        float d2 = oacc[jn][2]-mu1, d3 = oacc[jn][3]-mu1;
        v0 += d0*d0 + d1*d1;
        v1 += d2*d2 + d3*d3;
    }
    v0 += __shfl_xor_sync(0xffffffffu, v0, 1);
    v0 += __shfl_xor_sync(0xffffffffu, v0, 2);
    v1 += __shfl_xor_sync(0xffffffffu, v1, 1);
    v1 += __shfl_xor_sync(0xffffffffu, v1, 2);
    const float inv0 = rsqrtf(v0*(1.f/32.f) + 1e-5f);
    const float inv1 = rsqrtf(v1*(1.f/32.f) + 1e-5f);

    const int n0 = rowbase + gl;
    const size_t base0 = (size_t)(b*SEQ + n0)*EMB + h*HEADD;
    const size_t base1 = base0 + 8*EMB;
    #pragma unroll
    for (int jn=0;jn<4;jn++){
        const int c = jn*8 + tq*2;
        const float2 gs = *(const float2*)(gns + h*HEADD + c);
        const float2 gb2 = *(const float2*)(gnb + h*HEADD + c);
        float2 gg0 = *(const float2*)(g + base0 + c);
        float2 gg1 = *(const float2*)(g + base1 + c);
        float y0 = ((oacc[jn][0]-mu0)*inv0*gs.x + gb2.x) * swish_f(gg0.x);
        float y1 = ((oacc[jn][1]-mu0)*inv0*gs.y + gb2.y) * swish_f(gg0.y);
        float y2 = ((oacc[jn][2]-mu1)*inv1*gs.x + gb2.x) * swish_f(gg1.x);
        float y3 = ((oacc[jn][3]-mu1)*inv1*gs.y + gb2.y) * swish_f(gg1.y);
        uint32_t l01, h01 = pack2(y0, y1, l01);
        uint32_t l23, h23 = pack2(y2, y3, l23);
        *(uint32_t*)(zh + base0 + c) = h01;
        *(uint32_t*)(zl + base0 + c) = l01;
        *(uint32_t*)(zh + base1 + c) = h23;
        *(uint32_t*)(zl + base1 + c) = l23;
    }
}

// ---------------- rmsnorm (fused residual) + bf16 split out ------------------
__global__ __launch_bounds__(256)
void rmsnorm_kernel(const float* __restrict__ a, const float* __restrict__ b,
                    const float* __restrict__ scale, float* __restrict__ out,
                    __nv_bfloat16* __restrict__ outH, __nv_bfloat16* __restrict__ outL)
{
    const int row = blockIdx.x;
    const int tid = threadIdx.x;
    const size_t idx = (size_t)row*EMB + tid;
    float v = a[idx];
    if (b) v += b[idx];
    float sq = v*v;
    #pragma unroll
    for (int o=16;o;o>>=1) sq += __shfl_xor_sync(0xffffffffu, sq, o);
    __shared__ float ws[8];
    if ((tid & 31) == 0) ws[tid>>5] = sq;
    __syncthreads();
    float tot = 0.f;
    #pragma unroll
    for (int w=0; w<8; w++) tot += ws[w];
    float y = v * rsqrtf(tot*(1.f/256.f) + 1e-6f) * scale[tid];
    out[idx] = y;
    __nv_bfloat16 hh = __float2bfloat16(y);
    outH[idx] = hh;
    outL[idx] = __float2bfloat16(y - __bfloat162float(hh));
}

// ---------------- launcher ---------------------------------------------------
extern "C" void kernel_launch(void* const* d_in, const int* in_sizes, int n_in,
                              void* d_out, int out_size)
{
    (void)in_sizes; (void)n_in; (void)out_size;
    const float* action = (const float*)d_in[0];
    const float* obs    = (const float*)d_in[1];
    const float* w_enc  = (const float*)d_in[2];
    const float* ln0    = (const float*)d_in[3];
    const float* wq1    = (const float*)d_in[4];
    const float* wk1    = (const float*)d_in[5];
    const float* wv1    = (const float*)d_in[6];
    const float* wg1    = (const float*)d_in[7];
    const float* wo1    = (const float*)d_in[8];
    const float* gns1   = (const float*)d_in[9];
    const float* gnb1   = (const float*)d_in[10];
    const float* ln1    = (const float*)d_in[11];
    const float* wq2    = (const float*)d_in[12];
    const float* wk2    = (const float*)d_in[13];
    const float* wv2    = (const float*)d_in[14];
    const float* wg2    = (const float*)d_in[15];
    const float* wo2    = (const float*)d_in[16];
    const float* gns2   = (const float*)d_in[17];
    const float* gnb2   = (const float*)d_in[18];
    const float* ln2    = (const float*)d_in[19];
    const float* swg    = (const float*)d_in[20];
    const float* sw1    = (const float*)d_in[21];
    const float* sw2    = (const float*)d_in[22];
    const float* ln3    = (const float*)d_in[23];
    const float* hw1    = (const float*)d_in[24];
    const float* hb1    = (const float*)d_in[25];
    const float* hln    = (const float*)d_in[26];
    const float* hw2    = (const float*)d_in[27];
    const float* hb2    = (const float*)d_in[28];
    float* out = (float*)d_out;

    float *x,*qb,*kb,*vb,*gb,*zb,*tb;
    __nv_bfloat16 *xH,*xL,*oH,*oL,*zH,*zL,*aH,*aL,*wH,*wL;
    cudaGetSymbolAddress((void**)&x,  g_x);
    cudaGetSymbolAddress((void**)&qb, g_q);
    cudaGetSymbolAddress((void**)&kb, g_k);
    cudaGetSymbolAddress((void**)&vb, g_v);
    cudaGetSymbolAddress((void**)&gb, g_g);
    cudaGetSymbolAddress((void**)&zb, g_z);
    cudaGetSymbolAddress((void**)&tb, g_t);
    cudaGetSymbolAddress((void**)&xH, g_xH);
    cudaGetSymbolAddress((void**)&xL, g_xL);
    cudaGetSymbolAddress((void**)&oH, g_oH);
    cudaGetSymbolAddress((void**)&oL, g_oL);
    cudaGetSymbolAddress((void**)&zH, g_zH);
    cudaGetSymbolAddress((void**)&zL, g_zL);
    cudaGetSymbolAddress((void**)&aH, g_aH);
    cudaGetSymbolAddress((void**)&aL, g_aL);
    cudaGetSymbolAddress((void**)&wH, g_wH);
    cudaGetSymbolAddress((void**)&wL, g_wL);

    cudaFuncSetAttribute(hgemm<0>, cudaFuncAttributeMaxDynamicSharedMemorySize, SMEM_TOT);
    cudaFuncSetAttribute(hgemm<1>, cudaFuncAttributeMaxDynamicSharedMemorySize, SMEM_TOT);
    cudaFuncSetAttribute(hgemm<2>, cudaFuncAttributeMaxDynamicSharedMemorySize, SMEM_TOT);
    cudaFuncSetAttribute(hgemm<3>, cudaFuncAttributeMaxDynamicSharedMemorySize, SMEM_TOT);

    // ---- weight slots: blk*13 + {0..12}; 39 w_enc, 40 hw1, 41 hw2 ----
    const float* wsrc[13*3];
    const float* wlist1[13] = {wq1,wk1,wv1,wg1,wo1,wq2,wk2,wv2,wg2,wo2,swg,sw1,sw2};
    ConvW cw{};
    for (int blk=0; blk<3; blk++)
        for (int j=0; j<13; j++){
            cw.src[blk*13+j] = wlist1[j] + (size_t)blk*EMB*EMB;
            cw.sz[blk*13+j] = EMB*EMB;
        }
    (void)wsrc;
    cw.src[39] = w_enc; cw.sz[39] = ADIM*EMB;
    cw.src[40] = hw1;   cw.sz[40] = EMB*EMB;
    cw.src[41] = hw2;   cw.sz[41] = EMB*ADIM;

    conv_w<<<dim3(NSLOT,32),256>>>(cw, wH, wL);
    conv_a<<<2048,256>>>(action, aH, aL, MROWS*ADIM);
    conv_a<<<4096,256>>>(obs, oH, oL, MROWS*EMB);

    auto WHs = [&](int slot){ return (const __nv_bfloat16*)(wH + (size_t)slot*SLOT_SZ); };
    auto WLs = [&](int slot){ return (const __nv_bfloat16*)(wL + (size_t)slot*SLOT_SZ); };

    auto mk1 = [&](const __nv_bfloat16* ah, const __nv_bfloat16* al, int slot,
                   float* c, const float* bias, const float* aux,
                   __nv_bfloat16* ch, __nv_bfloat16* cl, int N, int K){
        GemmP p{};
        for (int i=0;i<4;i++){ p.AH[i]=ah; p.AL[i]=al; p.WH[i]=WHs(slot); p.WL[i]=WLs(slot); p.C[i]=c; }
        p.bias=bias; p.aux=aux; p.CH=ch; p.CL=cl; p.N=N; p.K=K;
        return p;
    };

    const dim3 g1(MROWS/128, 4);
    const dim3 g4(MROWS/128, 16);
    const dim3 gHead(MROWS/128, 1);
    const dim3 gAttn(SEQ/128, NHEAD, BATCH);

    // encoder
    hgemm<1><<<g1,256,SMEM_TOT>>>(mk1(aH, aL, 39, tb, nullptr, nullptr, nullptr, nullptr, EMB, ADIM));
    rmsnorm_kernel<<<MROWS,256>>>(tb, nullptr, ln0, x, xH, xL);

    for (int blk=0; blk<3; blk++){
        const int s0 = blk*13;
        const size_t vOff = (size_t)blk*EMB;

        // retention 1: q/k/v/g projections (batched)
        {
            GemmP p{};
            const int slots[4] = {s0+0, s0+1, s0+2, s0+3};
            float* cs[4] = {qb, kb, vb, gb};
            for (int i=0;i<4;i++){
                p.AH[i]=xH; p.AL[i]=xL;
                p.WH[i]=WHs(slots[i]); p.WL[i]=WLs(slots[i]); p.C[i]=cs[i];
            }
            p.N=EMB; p.K=EMB;
            hgemm<0><<<g4,256,SMEM_TOT>>>(p);
        }
        attn_tc<<<gAttn,256>>>(qb, kb, vb, gb, gns1+vOff, gnb1+vOff, zH, zL);
        hgemm<0><<<g1,256,SMEM_TOT>>>(mk1(zH, zL, s0+4, tb, nullptr, nullptr, nullptr, nullptr, EMB, EMB));
        rmsnorm_kernel<<<MROWS,256>>>(x, tb, ln1+vOff, x, xH, xL);

        // retention 2: k/v from x, q/g from obs (all batched in one launch)
        {
            GemmP p{};
            const int slots[4] = {s0+6, s0+7, s0+5, s0+8};   // wk2, wv2, wq2, wg2
            float* cs[4] = {kb, vb, qb, gb};
            const __nv_bfloat16* ahs[4] = {xH, xH, oH, oH};
            const __nv_bfloat16* als[4] = {xL, xL, oL, oL};
            for (int i=0;i<4;i++){
                p.AH[i]=ahs[i]; p.AL[i]=als[i];
                p.WH[i]=WHs(slots[i]); p.WL[i]=WLs(slots[i]); p.C[i]=cs[i];
            }
            p.N=EMB; p.K=EMB;
            hgemm<0><<<g4,256,SMEM_TOT>>>(p);
        }
        attn_tc<<<gAttn,256>>>(qb, kb, vb, gb, gns2+vOff, gnb2+vOff, zH, zL);
        hgemm<0><<<g1,256,SMEM_TOT>>>(mk1(zH, zL, s0+9, tb, nullptr, nullptr, nullptr, nullptr, EMB, EMB));
        rmsnorm_kernel<<<MROWS,256>>>(obs, tb, ln2+vOff, x, xH, xL);

        // swiglu
        hgemm<0><<<g1,256,SMEM_TOT>>>(mk1(xH, xL, s0+11, tb, nullptr, nullptr, nullptr, nullptr, EMB, EMB));
        hgemm<2><<<g1,256,SMEM_TOT>>>(mk1(xH, xL, s0+10, nullptr, nullptr, tb, zH, zL, EMB, EMB));
        hgemm<0><<<g1,256,SMEM_TOT>>>(mk1(zH, zL, s0+12, tb, nullptr, nullptr, nullptr, nullptr, EMB, EMB));
        rmsnorm_kernel<<<MROWS,256>>>(x, tb, ln3+vOff, x, xH, xL);
    }

    // head
    hgemm<1><<<g1,256,SMEM_TOT>>>(mk1(xH, xL, 40, tb, hb1, nullptr, nullptr, nullptr, EMB, EMB));
    rmsnorm_kernel<<<MROWS,256>>>(tb, nullptr, hln, zb, zH, zL);
    hgemm<3><<<gHead,256,SMEM_TOT>>>(mk1(zH, zL, 41, out, hb2, nullptr, nullptr, nullptr, ADIM, EMB));
}